// round 2
// baseline (speedup 1.0000x reference)
#include <cuda_runtime.h>
#include <cuda_bf16.h>
#include <math.h>

// Problem constants
#define BATCH 2
#define SEQ   2048
#define DMODEL 1024
#define NHEAD 16
#define DHEAD 64
#define DFF   4096
#define ROWS  (BATCH*SEQ)   // 4096

// ----------------------------------------------------------------------------
// Scratch (device globals; no allocations allowed)
// ----------------------------------------------------------------------------
__device__ float g_h   [(size_t)ROWS*DMODEL];      // rmsnorm output (reused)
__device__ float g_tmp [(size_t)ROWS*DMODEL];      // linear output before transpose
__device__ float g_q   [(size_t)ROWS*DMODEL];      // [B,H,S,DK]
__device__ float g_k   [(size_t)ROWS*DMODEL];
__device__ float g_v   [(size_t)ROWS*DMODEL];
__device__ float g_ctx [(size_t)ROWS*DMODEL];      // [B,S,D]
__device__ float g_x2  [(size_t)ROWS*DMODEL];      // post-attention residual
__device__ float g_u   [(size_t)ROWS*2*DFF];       // FFN up-proj  (134 MB)
__device__ float g_ffn [(size_t)ROWS*DFF];         // swiglu out   (67 MB)
__device__ float g_cos [SEQ*32];
__device__ float g_sin [SEQ*32];

// ----------------------------------------------------------------------------
// RoPE table (double precision: matches true math to ~1e-16; jax fp32 own error
// dominates the comparison at ~1e-4 in angle which is fine for 1e-3 rel_err)
// ----------------------------------------------------------------------------
__global__ void build_rope_table() {
    int idx = blockIdx.x * blockDim.x + threadIdx.x;
    if (idx >= SEQ * 32) return;
    int s = idx / 32, j = idx % 32;
    double invf = exp(-(double)j * (9.210340371976184 / 32.0)); // 10000^(-j/32)
    double a = (double)s * invf;
    g_cos[idx] = (float)cos(a);
    g_sin[idx] = (float)sin(a);
}

// ----------------------------------------------------------------------------
// RMSNorm: one block per row of 1024
// ----------------------------------------------------------------------------
__global__ __launch_bounds__(256) void rmsnorm_k(const float* __restrict__ x,
                                                 const float* __restrict__ g,
                                                 float* __restrict__ o) {
    int row = blockIdx.x;
    const float* xr = x + (size_t)row * DMODEL;
    float ss = 0.f;
    for (int c = threadIdx.x; c < DMODEL; c += 256) { float v = xr[c]; ss += v * v; }
    __shared__ float sm[8];
    for (int off = 16; off; off >>= 1) ss += __shfl_down_sync(0xffffffffu, ss, off);
    if ((threadIdx.x & 31) == 0) sm[threadIdx.x >> 5] = ss;
    __syncthreads();
    if (threadIdx.x < 8) {
        float v = sm[threadIdx.x];
        for (int off = 4; off; off >>= 1) v += __shfl_down_sync(0xffu, v, off);
        if (threadIdx.x == 0) sm[0] = v;
    }
    __syncthreads();
    float inv = 1.0f / sqrtf(sm[0] / (float)DMODEL + 1e-6f);
    float* orow = o + (size_t)row * DMODEL;
    for (int c = threadIdx.x; c < DMODEL; c += 256) orow[c] = xr[c] * inv * g[c];
}

// ----------------------------------------------------------------------------
// NT SGEMM: C[M,N] = A[M,K] @ B[N,K]^T (+ residual). 128x128x16 tile,
// 256 threads, 8x8 micro-tile. All dims assumed divisible (they are).
// ----------------------------------------------------------------------------
__global__ __launch_bounds__(256) void gemm_nt(const float* __restrict__ A,
                                               const float* __restrict__ B,
                                               const float* __restrict__ res,
                                               float* __restrict__ C,
                                               int M, int N, int K) {
    const int BM = 128, BN = 128, BK = 16;
    __shared__ float As[BK][BM];
    __shared__ float Bs[BK][BN];
    int bx = blockIdx.x, by = blockIdx.y;
    int tid = threadIdx.x;
    int tx = tid & 15, ty = tid >> 4;
    float acc[8][8] = {};
    const float* Atile = A + (size_t)by * BM * K;
    const float* Btile = B + (size_t)bx * BN * K;

    for (int k0 = 0; k0 < K; k0 += BK) {
#pragma unroll
        for (int it = 0; it < 2; it++) {
            int idx = tid + it * 256;           // 0..511 float4 slots
            int row = idx >> 2;                 // 0..127
            int c4  = (idx & 3) * 4;            // 0,4,8,12
            float4 va = *reinterpret_cast<const float4*>(Atile + (size_t)row * K + k0 + c4);
            As[c4 + 0][row] = va.x; As[c4 + 1][row] = va.y;
            As[c4 + 2][row] = va.z; As[c4 + 3][row] = va.w;
            float4 vb = *reinterpret_cast<const float4*>(Btile + (size_t)row * K + k0 + c4);
            Bs[c4 + 0][row] = vb.x; Bs[c4 + 1][row] = vb.y;
            Bs[c4 + 2][row] = vb.z; Bs[c4 + 3][row] = vb.w;
        }
        __syncthreads();
#pragma unroll
        for (int kk = 0; kk < BK; kk++) {
            float a[8], b[8];
            float4 a0 = *reinterpret_cast<const float4*>(&As[kk][ty * 8]);
            float4 a1 = *reinterpret_cast<const float4*>(&As[kk][ty * 8 + 4]);
            a[0]=a0.x; a[1]=a0.y; a[2]=a0.z; a[3]=a0.w;
            a[4]=a1.x; a[5]=a1.y; a[6]=a1.z; a[7]=a1.w;
            float4 b0 = *reinterpret_cast<const float4*>(&Bs[kk][tx * 8]);
            float4 b1 = *reinterpret_cast<const float4*>(&Bs[kk][tx * 8 + 4]);
            b[0]=b0.x; b[1]=b0.y; b[2]=b0.z; b[3]=b0.w;
            b[4]=b1.x; b[5]=b1.y; b[6]=b1.z; b[7]=b1.w;
#pragma unroll
            for (int i = 0; i < 8; i++)
#pragma unroll
                for (int j = 0; j < 8; j++) acc[i][j] += a[i] * b[j];
        }
        __syncthreads();
    }

#pragma unroll
    for (int i = 0; i < 8; i++) {
        int r = by * BM + ty * 8 + i;
#pragma unroll
        for (int j = 0; j < 8; j += 4) {
            int c = bx * BN + tx * 8 + j;
            float4 o;
            o.x = acc[i][j]; o.y = acc[i][j+1]; o.z = acc[i][j+2]; o.w = acc[i][j+3];
            if (res) {
                float4 rv = *reinterpret_cast<const float4*>(res + (size_t)r * N + c);
                o.x += rv.x; o.y += rv.y; o.z += rv.z; o.w += rv.w;
            }
            *reinterpret_cast<float4*>(C + (size_t)r * N + c) = o;
        }
    }
}

// ----------------------------------------------------------------------------
// RoPE + transpose [B,S,D] -> [B,H,S,DK]  (applyRope=0 for V: transpose only)
// ----------------------------------------------------------------------------
__global__ __launch_bounds__(256) void rope_tr(const float* __restrict__ lin,
                                               float* __restrict__ outp,
                                               int applyRope) {
    int row = blockIdx.x;              // 0..4095
    int b = row >> 11, s = row & 2047;
    const float* lr = lin + (size_t)row * DMODEL;
    for (int c = threadIdx.x; c < DMODEL; c += 256) {
        int h = c >> 6, dk = c & 63, j = dk & 31;
        float v = lr[c];
        float o = v;
        if (applyRope) {
            float cs = g_cos[s * 32 + j];
            float sn = g_sin[s * 32 + j];
            float rot = (dk < 32) ? -lr[c + 32] : lr[c - 32];
            o = v * cs + rot * sn;
        }
        outp[(((size_t)(b * NHEAD + h)) * SEQ + s) * DHEAD + dk] = o;
    }
}

// ----------------------------------------------------------------------------
// Flash attention, causal. Block = (q-tile of 64, one (b,h)). Key tiles of 32.
// 256 threads: 16x16. S partition: 4x2 per thread; O partition: 4x4 per thread.
// ----------------------------------------------------------------------------
__global__ __launch_bounds__(256) void flash_attn(const float* __restrict__ Q,
                                                  const float* __restrict__ K,
                                                  const float* __restrict__ V,
                                                  float* __restrict__ ctx) {
    int qt = blockIdx.x;           // 0..31
    int bh = blockIdx.y;           // 0..31
    int tid = threadIdx.x;
    int tx = tid & 15, ty = tid >> 4;

    __shared__ float Qs[64][64];
    __shared__ float KsT[64][33];
    __shared__ float Vs[32][64];
    __shared__ float Ss[64][33];
    __shared__ float rowm[64], rowl[64], rowsc[64];

    const size_t baseQ = ((size_t)bh * SEQ + (size_t)qt * 64) * DHEAD;
#pragma unroll
    for (int it = 0; it < 4; it++) {
        int idx = tid + it * 256;
        int r = idx >> 4, c4 = (idx & 15) * 4;
        *reinterpret_cast<float4*>(&Qs[r][c4]) =
            *reinterpret_cast<const float4*>(Q + baseQ + (size_t)r * 64 + c4);
    }
    if (tid < 64) { rowm[tid] = -1e30f; rowl[tid] = 0.f; }
    float o[4][4] = {};
    __syncthreads();

    int qbase = qt * 64;
    int ntile = 2 * (qt + 1);
    for (int kt = 0; kt < ntile; kt++) {
        int kb = kt * 32;
        const float* Kb = K + ((size_t)bh * SEQ + kb) * DHEAD;
        const float* Vb = V + ((size_t)bh * SEQ + kb) * DHEAD;
#pragma unroll
        for (int it = 0; it < 2; it++) {
            int idx = tid + it * 256;         // 512 float4
            int r = idx >> 4, c4 = (idx & 15) * 4;
            float4 kv = *reinterpret_cast<const float4*>(Kb + (size_t)r * 64 + c4);
            KsT[c4 + 0][r] = kv.x; KsT[c4 + 1][r] = kv.y;
            KsT[c4 + 2][r] = kv.z; KsT[c4 + 3][r] = kv.w;
            *reinterpret_cast<float4*>(&Vs[r][c4]) =
                *reinterpret_cast<const float4*>(Vb + (size_t)r * 64 + c4);
        }
        __syncthreads();

        float sacc[4][2] = {};
#pragma unroll 8
        for (int kk = 0; kk < 64; kk++) {
            float q0 = Qs[ty * 4 + 0][kk], q1 = Qs[ty * 4 + 1][kk];
            float q2 = Qs[ty * 4 + 2][kk], q3 = Qs[ty * 4 + 3][kk];
            float k0 = KsT[kk][tx * 2 + 0], k1 = KsT[kk][tx * 2 + 1];
            sacc[0][0] += q0 * k0; sacc[0][1] += q0 * k1;
            sacc[1][0] += q1 * k0; sacc[1][1] += q1 * k1;
            sacc[2][0] += q2 * k0; sacc[2][1] += q2 * k1;
            sacc[3][0] += q3 * k0; sacc[3][1] += q3 * k1;
        }
#pragma unroll
        for (int i = 0; i < 4; i++)
#pragma unroll
            for (int j = 0; j < 2; j++) {
                int r = ty * 4 + i, c = tx * 2 + j;
                int qg = qbase + r, kg = kb + c;
                Ss[r][c] = (kg <= qg) ? sacc[i][j] * 0.125f : -1e9f;
            }
        __syncthreads();

        if (tid < 64) {
            int r = tid;
            float m = rowm[r], mn = m;
            for (int c = 0; c < 32; c++) mn = fmaxf(mn, Ss[r][c]);
            float sc = expf(m - mn);
            float l = rowl[r] * sc;
            for (int c = 0; c < 32; c++) {
                float e = expf(Ss[r][c] - mn);
                Ss[r][c] = e; l += e;
            }
            rowm[r] = mn; rowl[r] = l; rowsc[r] = sc;
        }
        __syncthreads();

#pragma unroll
        for (int i = 0; i < 4; i++) {
            float sc = rowsc[ty * 4 + i];
#pragma unroll
            for (int j = 0; j < 4; j++) o[i][j] *= sc;
        }
#pragma unroll 8
        for (int kk = 0; kk < 32; kk++) {
            float p0 = Ss[ty * 4 + 0][kk], p1 = Ss[ty * 4 + 1][kk];
            float p2 = Ss[ty * 4 + 2][kk], p3 = Ss[ty * 4 + 3][kk];
            float v0 = Vs[kk][tx * 4 + 0], v1 = Vs[kk][tx * 4 + 1];
            float v2 = Vs[kk][tx * 4 + 2], v3 = Vs[kk][tx * 4 + 3];
            o[0][0] += p0 * v0; o[0][1] += p0 * v1; o[0][2] += p0 * v2; o[0][3] += p0 * v3;
            o[1][0] += p1 * v0; o[1][1] += p1 * v1; o[1][2] += p1 * v2; o[1][3] += p1 * v3;
            o[2][0] += p2 * v0; o[2][1] += p2 * v1; o[2][2] += p2 * v2; o[2][3] += p2 * v3;
            o[3][0] += p3 * v0; o[3][1] += p3 * v1; o[3][2] += p3 * v2; o[3][3] += p3 * v3;
        }
        __syncthreads();
    }

    int b = bh >> 4, h = bh & 15;
#pragma unroll
    for (int i = 0; i < 4; i++) {
        int r = ty * 4 + i;
        size_t grow = (size_t)b * SEQ + qbase + r;
        float invl = 1.0f / rowl[r];
#pragma unroll
        for (int j = 0; j < 4; j++)
            ctx[grow * DMODEL + h * 64 + tx * 4 + j] = o[i][j] * invl;
    }
}

// ----------------------------------------------------------------------------
// SwiGLU: ffn = u1 * silu(u2), u = [4096, 2*DFF]
// ----------------------------------------------------------------------------
__global__ __launch_bounds__(256) void swiglu_k(const float* __restrict__ u,
                                                float* __restrict__ f) {
    size_t i = (size_t)blockIdx.x * blockDim.x + threadIdx.x;
    if (i >= (size_t)ROWS * DFF) return;
    size_t row = i / DFF, col = i % DFF;
    float a = u[row * (2 * DFF) + col];
    float b = u[row * (2 * DFF) + DFF + col];
    f[i] = a * (b / (1.0f + expf(-b)));
}

// ----------------------------------------------------------------------------
// Launch
// ----------------------------------------------------------------------------
extern "C" void kernel_launch(void* const* d_in, const int* in_sizes, int n_in,
                              void* d_out, int out_size) {
    const float* x  = (const float*)d_in[0];
    // d_in[1] = mask (causal tril; handled analytically)
    const float* wq = (const float*)d_in[2];
    const float* wk = (const float*)d_in[3];
    const float* wv = (const float*)d_in[4];
    const float* wo = (const float*)d_in[5];
    const float* w1 = (const float*)d_in[6];
    const float* w2 = (const float*)d_in[7];
    const float* g1 = (const float*)d_in[8];
    const float* g2 = (const float*)d_in[9];
    float* out = (float*)d_out;

    static float *p_h=nullptr,*p_tmp=nullptr,*p_q=nullptr,*p_k=nullptr,*p_v=nullptr,
                 *p_ctx=nullptr,*p_x2=nullptr,*p_u=nullptr,*p_ffn=nullptr;
    if (!p_h) {
        cudaGetSymbolAddress((void**)&p_h,   g_h);
        cudaGetSymbolAddress((void**)&p_tmp, g_tmp);
        cudaGetSymbolAddress((void**)&p_q,   g_q);
        cudaGetSymbolAddress((void**)&p_k,   g_k);
        cudaGetSymbolAddress((void**)&p_v,   g_v);
        cudaGetSymbolAddress((void**)&p_ctx, g_ctx);
        cudaGetSymbolAddress((void**)&p_x2,  g_x2);
        cudaGetSymbolAddress((void**)&p_u,   g_u);
        cudaGetSymbolAddress((void**)&p_ffn, g_ffn);
    }

    build_rope_table<<<(SEQ * 32 + 255) / 256, 256>>>();

    // --- attention sublayer ---
    rmsnorm_k<<<ROWS, 256>>>(x, g1, p_h);

    dim3 gproj(DMODEL / 128, ROWS / 128);   // (8, 32)
    gemm_nt<<<gproj, 256>>>(p_h, wq, nullptr, p_tmp, ROWS, DMODEL, DMODEL);
    rope_tr<<<ROWS, 256>>>(p_tmp, p_q, 1);
    gemm_nt<<<gproj, 256>>>(p_h, wk, nullptr, p_tmp, ROWS, DMODEL, DMODEL);
    rope_tr<<<ROWS, 256>>>(p_tmp, p_k, 1);
    gemm_nt<<<gproj, 256>>>(p_h, wv, nullptr, p_tmp, ROWS, DMODEL, DMODEL);
    rope_tr<<<ROWS, 256>>>(p_tmp, p_v, 0);

    flash_attn<<<dim3(SEQ / 64, BATCH * NHEAD), 256>>>(p_q, p_k, p_v, p_ctx);

    gemm_nt<<<gproj, 256>>>(p_ctx, wo, x, p_x2, ROWS, DMODEL, DMODEL);

    // --- FFN sublayer ---
    rmsnorm_k<<<ROWS, 256>>>(p_x2, g2, p_h);
    dim3 gup(2 * DFF / 128, ROWS / 128);    // (64, 32)
    gemm_nt<<<gup, 256>>>(p_h, w1, nullptr, p_u, ROWS, 2 * DFF, DMODEL);
    swiglu_k<<<(unsigned)(((size_t)ROWS * DFF + 255) / 256), 256>>>(p_u, p_ffn);
    dim3 gdown(DMODEL / 128, ROWS / 128);   // (8, 32)
    gemm_nt<<<gdown, 256>>>(p_ffn, w2, p_x2, out, ROWS, DMODEL, DFF);
}